// round 1
// baseline (speedup 1.0000x reference)
#include <cuda_runtime.h>
#include <cuda_bf16.h>

// Problem constants
#define BB   64
#define HH   768
#define MAXL 256
#define QL   16
#define LA   272   // MAXL + QL
#define NC   3
#define OUTC 2003  // NC + 1000 + 1000

// ---------------- scratch (device globals; no allocation) ----------------
__device__ float g_X   [BB * LA * HH];     // xa / xb (B,S,H)
__device__ float g_Q   [BB * LA * HH];
__device__ float g_K   [BB * LA * HH];
__device__ float g_V   [BB * LA * HH];
__device__ float g_ATTN[BB * HH * HH];     // covers SxS (272^2) and HxH (768^2)
__device__ float g_TSA [BB * LA * HH];     // time-SA output
__device__ float g_FSA [BB * HH * LA];     // feature-SA raw (d, l)
__device__ float g_T   [BB * LA * 100];
__device__ float g_F   [BB * LA * 100];
__device__ float g_TF  [BB * 100 * 100];
__device__ float g_H   [BB * 2 * HH];
__device__ float g_T1  [BB * HH];

// ---------------- generic strided batched GEMM ----------------
// C[b, m, n] = alpha * sum_k A[b*sAb + m*sAm + k*sAk] * B[b*sBb + k*sBk + n*sBn]
//              + (bias ? bias[n] : 0)
// tile 64x64, 16x16 threads, 4x4 per thread, K-tile 16
#define TS 64
#define KT 16

__global__ void gemm_g(const float* __restrict__ A, const float* __restrict__ Bm,
                       float* __restrict__ C, const float* __restrict__ bias,
                       int M, int N, int K,
                       long sAb, long sAm, long sAk,
                       long sBb, long sBk, long sBn,
                       long sCb, long sCm,
                       float alpha)
{
    __shared__ float As[KT][TS];   // [k][m]
    __shared__ float Bs[KT][TS];   // [k][n]

    const int bm = blockIdx.y * TS;
    const int bn = blockIdx.x * TS;
    const int b  = blockIdx.z;
    A  += (long)b * sAb;
    Bm += (long)b * sBb;
    C  += (long)b * sCb;

    const int tx  = threadIdx.x;           // 0..15
    const int ty  = threadIdx.y;           // 0..15
    const int tid = ty * 16 + tx;

    float acc[4][4];
    #pragma unroll
    for (int i = 0; i < 4; i++)
        #pragma unroll
        for (int j = 0; j < 4; j++) acc[i][j] = 0.f;

    for (int k0 = 0; k0 < K; k0 += KT) {
        // load A tile (64 m x 16 k), 1024 elems / 256 threads = 4 each
        #pragma unroll
        for (int t = 0; t < 4; t++) {
            int e  = tid + t * 256;
            int m  = e % TS;
            int kk = e / TS;
            int gm = bm + m, gk = k0 + kk;
            As[kk][m] = (gm < M && gk < K) ? A[(long)gm * sAm + (long)gk * sAk] : 0.f;
        }
        #pragma unroll
        for (int t = 0; t < 4; t++) {
            int e  = tid + t * 256;
            int n  = e % TS;
            int kk = e / TS;
            int gn = bn + n, gk = k0 + kk;
            Bs[kk][n] = (gn < N && gk < K) ? Bm[(long)gk * sBk + (long)gn * sBn] : 0.f;
        }
        __syncthreads();

        #pragma unroll
        for (int kk = 0; kk < KT; kk++) {
            float a[4], bv[4];
            #pragma unroll
            for (int i = 0; i < 4; i++) a[i]  = As[kk][ty + 16 * i];
            #pragma unroll
            for (int j = 0; j < 4; j++) bv[j] = Bs[kk][tx + 16 * j];
            #pragma unroll
            for (int i = 0; i < 4; i++)
                #pragma unroll
                for (int j = 0; j < 4; j++)
                    acc[i][j] += a[i] * bv[j];
        }
        __syncthreads();
    }

    #pragma unroll
    for (int i = 0; i < 4; i++) {
        int gm = bm + ty + 16 * i;
        if (gm >= M) continue;
        #pragma unroll
        for (int j = 0; j < 4; j++) {
            int gn = bn + tx + 16 * j;
            if (gn >= N) continue;
            float v = acc[i][j] * alpha;
            if (bias) v += bias[gn];
            C[(long)gm * sCm + gn] = v;
        }
    }
}

// ---------------- row softmax (in place) ----------------
__global__ void softmax_rows(float* __restrict__ x, int n)
{
    long r = blockIdx.x;
    float* p = x + r * (long)n;
    __shared__ float sd[256];
    int t = threadIdx.x;

    float m = -3.4e38f;
    for (int i = t; i < n; i += 256) m = fmaxf(m, p[i]);
    sd[t] = m; __syncthreads();
    for (int s = 128; s > 0; s >>= 1) { if (t < s) sd[t] = fmaxf(sd[t], sd[t + s]); __syncthreads(); }
    m = sd[0]; __syncthreads();

    float sum = 0.f;
    for (int i = t; i < n; i += 256) { float e = __expf(p[i] - m); p[i] = e; sum += e; }
    sd[t] = sum; __syncthreads();
    for (int s = 128; s > 0; s >>= 1) { if (t < s) sd[t] += sd[t + s]; __syncthreads(); }
    float inv = 1.0f / sd[0];

    for (int i = t; i < n; i += 256) p[i] *= inv;
}

// ---------------- copy tokens[:,1:,:] -> X ----------------
__global__ void strip_first(const float* __restrict__ src, float* __restrict__ dst,
                            int rows_in, int rows_out)
{
    long i = (long)blockIdx.x * blockDim.x + threadIdx.x;
    long total = (long)BB * rows_out * HH;
    if (i >= total) return;
    int d = (int)(i % HH);
    long tmp = i / HH;
    int l = (int)(tmp % rows_out);
    int b = (int)(tmp / rows_out);
    dst[i] = src[((long)b * rows_in + (l + 1)) * HH + d];
}

// ---------------- build h = concat(tokens[:,0,:], cls_tokens[:,0,:]) ----------------
__global__ void build_h(const float* __restrict__ tok, const float* __restrict__ ctok,
                        float* __restrict__ h)
{
    int i = blockIdx.x * blockDim.x + threadIdx.x;
    if (i >= BB * 2 * HH) return;
    int c = i % (2 * HH);
    int b = i / (2 * HH);
    h[i] = (c < HH) ? tok[(long)b * (LA + 1) * HH + c]
                    : ctok[(long)b * (MAXL + 1) * HH + (c - HH)];
}

// ---------------- host helpers ----------------
static void launch_gemm(const float* A, const float* Bm, float* C, const float* bias,
                        int M, int N, int K, int batch,
                        long sAb, long sAm, long sAk,
                        long sBb, long sBk, long sBn,
                        long sCb, long sCm, float alpha)
{
    dim3 grid((N + TS - 1) / TS, (M + TS - 1) / TS, batch);
    dim3 blk(16, 16);
    gemm_g<<<grid, blk>>>(A, Bm, C, bias, M, N, K,
                          sAb, sAm, sAk, sBb, sBk, sBn, sCb, sCm, alpha);
}

template <typename T>
static float* sym(T& s)
{
    void* p = nullptr;
    cudaGetSymbolAddress(&p, s);
    return (float*)p;
}

// Process one branch: tokens_full (B, S+1, H), feature-dim F (=S), output cols at out_off
static void run_branch(const float* tokens_full, int S,
                       const float* qkv_w, const float* qkv_b,     // (3,H,H)
                       const float* fqkv_w, const float* fqkv_b,   // (3,S,S)
                       const float* tW_w, const float* tW_b,       // (H,100)
                       const float* fW_w, const float* fW_b,       // (H,100)
                       const float* ft_w, const float* ft_b,       // (10000,1000)
                       float* out, int out_off)
{
    float* X    = sym(g_X);
    float* Q    = sym(g_Q);
    float* Kb   = sym(g_K);
    float* V    = sym(g_V);
    float* ATTN = sym(g_ATTN);
    float* TSA  = sym(g_TSA);
    float* FSA  = sym(g_FSA);
    float* Tm   = sym(g_T);
    float* Fm   = sym(g_F);
    float* TF   = sym(g_TF);

    const long SH = (long)S * HH;
    const float iscH = rsqrtf((float)HH);
    const float iscS = rsqrtf((float)S);

    // X = tokens_full[:, 1:, :]
    {
        long total = (long)BB * S * HH;
        strip_first<<<(int)((total + 255) / 256), 256>>>(tokens_full, X, S + 1, S);
    }

    // ---- time self-attention ----
    // Q/K/V = X @ w[j] + b[j] : single big GEMM M=B*S, N=H, K=H
    float* qkv[3] = {Q, Kb, V};
    for (int j = 0; j < 3; j++) {
        launch_gemm(X, qkv_w + (long)j * HH * HH, qkv[j], qkv_b + (long)j * HH,
                    BB * S, HH, HH, 1,
                    0, HH, 1,     // A strides
                    0, HH, 1,     // B strides
                    0, HH, 1.0f);
    }
    // scores[b,l,m] = Q[b,l,:] . K[b,m,:] * 1/sqrt(H)
    launch_gemm(Q, Kb, ATTN, nullptr, S, S, HH, BB,
                SH, HH, 1,
                SH, 1, HH,
                (long)S * S, S, iscH);
    softmax_rows<<<BB * S, 256>>>(ATTN, S);
    // TSA = attn @ V
    launch_gemm(ATTN, V, TSA, nullptr, S, HH, S, BB,
                (long)S * S, S, 1,
                SH, HH, 1,
                SH, HH, 1.0f);

    // ---- feature self-attention (on X^T, shape (H, S)) ----
    // Qf[b,d,m] = sum_l X[b,l,d] * fw[j][l,m] + fb[j][m]
    for (int j = 0; j < 3; j++) {
        launch_gemm(X, fqkv_w + (long)j * S * S, qkv[j], fqkv_b + (long)j * S,
                    HH, S, S, BB,
                    SH, 1, HH,       // A: (m=d) stride 1, (k=l) stride H
                    0, S, 1,
                    SH, S, 1.0f);
    }
    // scoresF[b,d,e] = Qf[b,d,:] . Kf[b,e,:] * 1/sqrt(S)
    launch_gemm(Q, Kb, ATTN, nullptr, HH, HH, S, BB,
                SH, S, 1,
                SH, 1, S,
                (long)HH * HH, HH, iscS);
    softmax_rows<<<BB * HH, 256>>>(ATTN, HH);
    // FSA[b,d,l] = attnF @ Vf
    launch_gemm(ATTN, V, FSA, nullptr, HH, S, HH, BB,
                (long)HH * HH, HH, 1,
                SH, S, 1,
                SH, S, 1.0f);

    // ---- projections to 100 ----
    // T = TSA @ tW + tb : M=B*S, N=100, K=H
    launch_gemm(TSA, tW_w, Tm, tW_b, BB * S, 100, HH, 1,
                0, HH, 1, 0, 100, 1, 0, 100, 1.0f);
    // F[b,l,n] = sum_d FSA[b,d,l] * fW[d,n] + fb[n]
    launch_gemm(FSA, fW_w, Fm, fW_b, S, 100, HH, BB,
                SH, 1, S,
                0, 100, 1,
                (long)S * 100, 100, 1.0f);

    // ---- TF[b,m,n] = sum_l T[b,l,m] * F[b,l,n] ----
    launch_gemm(Tm, Fm, TF, nullptr, 100, 100, S, BB,
                (long)S * 100, 1, 100,
                (long)S * 100, 100, 1,
                10000, 100, 1.0f);

    // ---- out[:, out_off:out_off+1000] = TF.reshape(B,10000) @ ft_w + ft_b ----
    launch_gemm(TF, ft_w, out + out_off, ft_b, BB, 1000, 10000, 1,
                0, 10000, 1,
                0, 1000, 1,
                0, OUTC, 1.0f);
}

extern "C" void kernel_launch(void* const* d_in, const int* in_sizes, int n_in,
                              void* d_out, int out_size)
{
    const float* tokens     = (const float*)d_in[0];
    const float* cls_tokens = (const float*)d_in[1];
    const float* a_qkv_w    = (const float*)d_in[2];
    const float* a_qkv_b    = (const float*)d_in[3];
    const float* af_qkv_w   = (const float*)d_in[4];
    const float* af_qkv_b   = (const float*)d_in[5];
    const float* b_qkv_w    = (const float*)d_in[6];
    const float* b_qkv_b    = (const float*)d_in[7];
    const float* bf_qkv_w   = (const float*)d_in[8];
    const float* bf_qkv_b   = (const float*)d_in[9];
    const float* atW_w      = (const float*)d_in[10];
    const float* atW_b      = (const float*)d_in[11];
    const float* afW_w      = (const float*)d_in[12];
    const float* afW_b      = (const float*)d_in[13];
    const float* btW_w      = (const float*)d_in[14];
    const float* btW_b      = (const float*)d_in[15];
    const float* bfW_w      = (const float*)d_in[16];
    const float* bfW_b      = (const float*)d_in[17];
    const float* aft_w      = (const float*)d_in[18];
    const float* aft_b      = (const float*)d_in[19];
    const float* bft_w      = (const float*)d_in[20];
    const float* bft_b      = (const float*)d_in[21];
    const float* fnn1_w     = (const float*)d_in[22];
    const float* fnn1_b     = (const float*)d_in[23];
    const float* fnn2_w     = (const float*)d_in[24];
    const float* fnn2_b     = (const float*)d_in[25];

    float* out = (float*)d_out;

    // branch A (tokens, S = LA = 272) -> out cols [3, 1003)
    run_branch(tokens, LA, a_qkv_w, a_qkv_b, af_qkv_w, af_qkv_b,
               atW_w, atW_b, afW_w, afW_b, aft_w, aft_b, out, NC);

    // branch B (cls_tokens, S = MAXL = 256) -> out cols [1003, 2003)
    run_branch(cls_tokens, MAXL, b_qkv_w, b_qkv_b, bf_qkv_w, bf_qkv_b,
               btW_w, btW_b, bfW_w, bfW_b, bft_w, bft_b, out, NC + 1000);

    // ---- FNN head -> out cols [0, 3) ----
    float* Hc = sym(g_H);
    float* T1 = sym(g_T1);
    build_h<<<(BB * 2 * HH + 255) / 256, 256>>>(tokens, cls_tokens, Hc);
    // T1 = H @ fnn1_w + fnn1_b : M=64, N=768, K=1536
    launch_gemm(Hc, fnn1_w, T1, fnn1_b, BB, HH, 2 * HH, 1,
                0, 2 * HH, 1, 0, HH, 1, 0, HH, 1.0f);
    // predicts = T1 @ fnn2_w + fnn2_b : M=64, N=3, K=768 -> out cols [0,3)
    launch_gemm(T1, fnn2_w, out, fnn2_b, BB, NC, HH, 1,
                0, HH, 1, 0, NC, 1, 0, OUTC, 1.0f);
}

// round 11
// speedup vs baseline: 2.6672x; 2.6672x over previous
#include <cuda_runtime.h>
#include <stdint.h>

// Problem constants
#define BB   64
#define HH   768
#define MAXL 256
#define QL   16
#define LA   272   // MAXL + QL
#define NC   3
#define OUTC 2003  // NC + 1000 + 1000

// GEMM tiling
#define BM 128
#define BN 128
#define BK 16
#define RS 134          // padded smem row stride (floats): conflict-free STS both modes
#define NSPLIT 16

// ---------------- scratch (device globals; no allocation) ----------------
__device__ float g_X   [BB * LA * HH];
__device__ float g_Q   [BB * LA * HH];
__device__ float g_K   [BB * LA * HH];
__device__ float g_V   [BB * LA * HH];
__device__ float g_ATTN[BB * HH * HH];
__device__ float g_TSA [BB * LA * HH];
__device__ float g_FSA [BB * HH * LA];
__device__ float g_T   [BB * LA * 100];
__device__ float g_F   [BB * LA * 100];
__device__ float g_TF  [BB * 100 * 100];
__device__ float g_H   [BB * 2 * HH];
__device__ float g_T1  [BB * HH];
__device__ float g_SPL [NSPLIT * BB * 1000];

__device__ __forceinline__ unsigned f2tf32(float x)
{
    unsigned u;
    asm("cvt.rna.tf32.f32 %0, %1;" : "=r"(u) : "f"(x));
    return u;
}

__device__ __forceinline__ void mma_tf32(float* d, const unsigned* a, unsigned b0, unsigned b1)
{
    asm("mma.sync.aligned.m16n8k8.row.col.f32.tf32.tf32.f32 "
        "{%0,%1,%2,%3}, {%4,%5,%6,%7}, {%8,%9}, {%0,%1,%2,%3};\n"
        : "+f"(d[0]), "+f"(d[1]), "+f"(d[2]), "+f"(d[3])
        : "r"(a[0]), "r"(a[1]), "r"(a[2]), "r"(a[3]), "r"(b0), "r"(b1));
}

// ---------------- generic strided batched TF32 tensor-core GEMM ----------------
// C[b, m, n] = alpha * sum_k A[.] * B[.] + bias[n]
// if splitK > 0: batch index bz is the split index; C += bz*sCb; k in [bz*splitK, ...)
// NOTE: no min-blocks hint — the live register set (~150+) must not be capped
// at 128 regs or ptxas spills into the mainloop (LDL/STL every k-step).
__global__ __launch_bounds__(256) void gemm_tf32(
    const float* __restrict__ A, const float* __restrict__ Bm,
    float* __restrict__ C, const float* __restrict__ bias,
    int M, int N, int K,
    long sAb, long sAm, long sAk,
    long sBb, long sBk, long sBn,
    long sCb, long sCm,
    float alpha, int splitK)
{
    __shared__ float As[BK * RS];
    __shared__ float Bs[BK * RS];

    const int bz = blockIdx.z;
    int kBeg = 0, kEnd = K;
    if (splitK > 0) {
        kBeg = bz * splitK;
        kEnd = min(K, kBeg + splitK);
        C += (long)bz * sCb;
    } else {
        A  += (long)bz * sAb;
        Bm += (long)bz * sBb;
        C  += (long)bz * sCb;
    }

    const int bm = blockIdx.y * BM;
    const int bn = blockIdx.x * BN;
    const int tid  = threadIdx.x;
    const int lane = tid & 31;
    const int wid  = tid >> 5;
    const int wm   = wid & 3;    // 4 m-warps  -> 32 rows each
    const int wn   = wid >> 2;   // 2 n-warps  -> 64 cols each
    const int g    = lane >> 2;  // 0..7
    const int t4   = lane & 3;   // 0..3

    // Per-operand load indexing mode: k-fast when k-stride is 1 (coalesced),
    // else row-fast (coalesced when row-stride is 1).
    const bool aKf = (sAk == 1);
    const bool bKf = (sBk == 1);

    int amI[8], akI[8], bnI[8], bkI[8];
    #pragma unroll
    for (int t = 0; t < 8; t++) {
        int e = tid + t * 256;     // 0..2047
        amI[t] = aKf ? (e >> 4)  : (e & 127);
        akI[t] = aKf ? (e & 15)  : (e >> 7);
        bnI[t] = bKf ? (e >> 4)  : (e & 127);
        bkI[t] = bKf ? (e & 15)  : (e >> 7);
    }

    float acc[2][8][4];
    #pragma unroll
    for (int i = 0; i < 2; i++)
        #pragma unroll
        for (int j = 0; j < 8; j++)
            #pragma unroll
            for (int q = 0; q < 4; q++) acc[i][j][q] = 0.f;

    float pa[8], pb[8];

    // prologue load
    #pragma unroll
    for (int t = 0; t < 8; t++) {
        int gm = bm + amI[t], gka = kBeg + akI[t];
        pa[t] = (gm < M && gka < kEnd) ? A[(long)gm * sAm + (long)gka * sAk] : 0.f;
        int gn = bn + bnI[t], gkb = kBeg + bkI[t];
        pb[t] = (gn < N && gkb < kEnd) ? Bm[(long)gkb * sBk + (long)gn * sBn] : 0.f;
    }

    for (int k0 = kBeg; k0 < kEnd; k0 += BK) {
        // commit prefetched tile to smem (convert to tf32 bits)
        #pragma unroll
        for (int t = 0; t < 8; t++) {
            As[akI[t] * RS + amI[t]] = __uint_as_float(f2tf32(pa[t]));
            Bs[bkI[t] * RS + bnI[t]] = __uint_as_float(f2tf32(pb[t]));
        }
        __syncthreads();

        // prefetch next tile while computing
        int kn = k0 + BK;
        if (kn < kEnd) {
            #pragma unroll
            for (int t = 0; t < 8; t++) {
                int gm = bm + amI[t], gka = kn + akI[t];
                pa[t] = (gm < M && gka < kEnd) ? A[(long)gm * sAm + (long)gka * sAk] : 0.f;
                int gn = bn + bnI[t], gkb = kn + bkI[t];
                pb[t] = (gn < N && gkb < kEnd) ? Bm[(long)gkb * sBk + (long)gn * sBn] : 0.f;
            }
        }

        // compute: two k8 steps
        #pragma unroll
        for (int ks = 0; ks < BK; ks += 8) {
            unsigned a[2][4];
            #pragma unroll
            for (int tm = 0; tm < 2; tm++) {
                int mr = wm * 32 + tm * 16;
                a[tm][0] = __float_as_uint(As[(ks + t4    ) * RS + mr + g    ]);
                a[tm][1] = __float_as_uint(As[(ks + t4    ) * RS + mr + g + 8]);
                a[tm][2] = __float_as_uint(As[(ks + t4 + 4) * RS + mr + g    ]);
                a[tm][3] = __float_as_uint(As[(ks + t4 + 4) * RS + mr + g + 8]);
            }
            #pragma unroll
            for (int tn = 0; tn < 8; tn++) {
                int nc = wn * 64 + tn * 8 + g;
                unsigned b0 = __float_as_uint(Bs[(ks + t4    ) * RS + nc]);
                unsigned b1 = __float_as_uint(Bs[(ks + t4 + 4) * RS + nc]);
                mma_tf32(acc[0][tn], a[0], b0, b1);
                mma_tf32(acc[1][tn], a[1], b0, b1);
            }
        }
        __syncthreads();
    }

    // epilogue
    #pragma unroll
    for (int tm = 0; tm < 2; tm++) {
        int r0 = bm + wm * 32 + tm * 16 + g;
        int r1 = r0 + 8;
        #pragma unroll
        for (int tn = 0; tn < 8; tn++) {
            int cb = bn + wn * 64 + tn * 8 + 2 * t4;
            float v0 = acc[tm][tn][0] * alpha;
            float v1 = acc[tm][tn][1] * alpha;
            float v2 = acc[tm][tn][2] * alpha;
            float v3 = acc[tm][tn][3] * alpha;
            if (bias) {
                float b0 = (cb     < N) ? bias[cb]     : 0.f;
                float b1 = (cb + 1 < N) ? bias[cb + 1] : 0.f;
                v0 += b0; v1 += b1; v2 += b0; v3 += b1;
            }
            if (r0 < M) {
                if (cb     < N) C[(long)r0 * sCm + cb    ] = v0;
                if (cb + 1 < N) C[(long)r0 * sCm + cb + 1] = v1;
            }
            if (r1 < M) {
                if (cb     < N) C[(long)r1 * sCm + cb    ] = v2;
                if (cb + 1 < N) C[(long)r1 * sCm + cb + 1] = v3;
            }
        }
    }
}

// ---------------- split-K reduction (deterministic) ----------------
__global__ void splitk_reduce(const float* __restrict__ part, const float* __restrict__ bias,
                              float* __restrict__ out, long sCm)
{
    int i = blockIdx.x * 256 + threadIdx.x;  // over 64*1000
    if (i >= BB * 1000) return;
    int m = i / 1000, n = i % 1000;
    float s = bias[n];
    #pragma unroll
    for (int sp = 0; sp < NSPLIT; sp++) s += part[(long)sp * (BB * 1000) + i];
    out[(long)m * sCm + n] = s;
}

// ---------------- row softmax (in place) ----------------
__global__ void softmax_rows(float* __restrict__ x, int n)
{
    long r = blockIdx.x;
    float* p = x + r * (long)n;
    __shared__ float sd[256];
    int t = threadIdx.x;

    float m = -3.4e38f;
    for (int i = t; i < n; i += 256) m = fmaxf(m, p[i]);
    sd[t] = m; __syncthreads();
    for (int s = 128; s > 0; s >>= 1) { if (t < s) sd[t] = fmaxf(sd[t], sd[t + s]); __syncthreads(); }
    m = sd[0]; __syncthreads();

    float sum = 0.f;
    for (int i = t; i < n; i += 256) { float e = __expf(p[i] - m); p[i] = e; sum += e; }
    sd[t] = sum; __syncthreads();
    for (int s = 128; s > 0; s >>= 1) { if (t < s) sd[t] += sd[t + s]; __syncthreads(); }
    float inv = 1.0f / sd[0];

    for (int i = t; i < n; i += 256) p[i] *= inv;
}

// ---------------- copy tokens[:,1:,:] -> X ----------------
__global__ void strip_first(const float* __restrict__ src, float* __restrict__ dst,
                            int rows_in, int rows_out)
{
    long i = (long)blockIdx.x * blockDim.x + threadIdx.x;
    long total = (long)BB * rows_out * HH;
    if (i >= total) return;
    int d = (int)(i % HH);
    long tmp = i / HH;
    int l = (int)(tmp % rows_out);
    int b = (int)(tmp / rows_out);
    dst[i] = src[((long)b * rows_in + (l + 1)) * HH + d];
}

// ---------------- build h = concat(tokens[:,0,:], cls_tokens[:,0,:]) ----------------
__global__ void build_h(const float* __restrict__ tok, const float* __restrict__ ctok,
                        float* __restrict__ h)
{
    int i = blockIdx.x * blockDim.x + threadIdx.x;
    if (i >= BB * 2 * HH) return;
    int c = i % (2 * HH);
    int b = i / (2 * HH);
    h[i] = (c < HH) ? tok[(long)b * (LA + 1) * HH + c]
                    : ctok[(long)b * (MAXL + 1) * HH + (c - HH)];
}

// ---------------- host helpers ----------------
static void launch_gemm(const float* A, const float* Bm, float* C, const float* bias,
                        int M, int N, int K, int batch,
                        long sAb, long sAm, long sAk,
                        long sBb, long sBk, long sBn,
                        long sCb, long sCm, float alpha, int splitK = 0)
{
    dim3 grid((N + BN - 1) / BN, (M + BM - 1) / BM, splitK > 0 ? NSPLIT : batch);
    gemm_tf32<<<grid, 256>>>(A, Bm, C, bias, M, N, K,
                             sAb, sAm, sAk, sBb, sBk, sBn, sCb, sCm, alpha, splitK);
}

template <typename T>
static float* sym(T& s)
{
    void* p = nullptr;
    cudaGetSymbolAddress(&p, s);
    return (float*)p;
}

static void run_branch(const float* tokens_full, int S,
                       const float* qkv_w, const float* qkv_b,
                       const float* fqkv_w, const float* fqkv_b,
                       const float* tW_w, const float* tW_b,
                       const float* fW_w, const float* fW_b,
                       const float* ft_w, const float* ft_b,
                       float* out, int out_off)
{
    float* X    = sym(g_X);
    float* Q    = sym(g_Q);
    float* Kb   = sym(g_K);
    float* V    = sym(g_V);
    float* ATTN = sym(g_ATTN);
    float* TSA  = sym(g_TSA);
    float* FSA  = sym(g_FSA);
    float* Tm   = sym(g_T);
    float* Fm   = sym(g_F);
    float* TF   = sym(g_TF);
    float* SPL  = sym(g_SPL);

    const long SH = (long)S * HH;
    const float iscH = rsqrtf((float)HH);
    const float iscS = rsqrtf((float)S);

    {
        long total = (long)BB * S * HH;
        strip_first<<<(int)((total + 255) / 256), 256>>>(tokens_full, X, S + 1, S);
    }

    // ---- time self-attention ----
    float* qkv[3] = {Q, Kb, V};
    for (int j = 0; j < 3; j++) {
        launch_gemm(X, qkv_w + (long)j * HH * HH, qkv[j], qkv_b + (long)j * HH,
                    BB * S, HH, HH, 1,
                    0, HH, 1,
                    0, HH, 1,
                    0, HH, 1.0f);
    }
    launch_gemm(Q, Kb, ATTN, nullptr, S, S, HH, BB,
                SH, HH, 1,
                SH, 1, HH,
                (long)S * S, S, iscH);
    softmax_rows<<<BB * S, 256>>>(ATTN, S);
    launch_gemm(ATTN, V, TSA, nullptr, S, HH, S, BB,
                (long)S * S, S, 1,
                SH, HH, 1,
                SH, HH, 1.0f);

    // ---- feature self-attention ----
    for (int j = 0; j < 3; j++) {
        launch_gemm(X, fqkv_w + (long)j * S * S, qkv[j], fqkv_b + (long)j * S,
                    HH, S, S, BB,
                    SH, 1, HH,
                    0, S, 1,
                    SH, S, 1.0f);
    }
    launch_gemm(Q, Kb, ATTN, nullptr, HH, HH, S, BB,
                SH, S, 1,
                SH, 1, S,
                (long)HH * HH, HH, iscS);
    softmax_rows<<<BB * HH, 256>>>(ATTN, HH);
    launch_gemm(ATTN, V, FSA, nullptr, HH, S, HH, BB,
                (long)HH * HH, HH, 1,
                SH, S, 1,
                SH, S, 1.0f);

    // ---- projections to 100 ----
    launch_gemm(TSA, tW_w, Tm, tW_b, BB * S, 100, HH, 1,
                0, HH, 1, 0, 100, 1, 0, 100, 1.0f);
    launch_gemm(FSA, fW_w, Fm, fW_b, S, 100, HH, BB,
                SH, 1, S,
                0, 100, 1,
                (long)S * 100, 100, 1.0f);

    // ---- TF[b,m,n] = sum_l T[b,l,m] * F[b,l,n] ----
    launch_gemm(Tm, Fm, TF, nullptr, 100, 100, S, BB,
                (long)S * 100, 1, 100,
                (long)S * 100, 100, 1,
                10000, 100, 1.0f);

    // ---- big final GEMM via deterministic split-K ----
    // partial[sp] = TF @ ft_w over k-chunk sp
    int chunk = ((10000 + NSPLIT * BK - 1) / (NSPLIT * BK)) * BK;  // 640
    launch_gemm(TF, ft_w, SPL, nullptr, BB, 1000, 10000, 1,
                0, 10000, 1,
                0, 1000, 1,
                (long)BB * 1000, 1000, 1.0f, chunk);
    splitk_reduce<<<(BB * 1000 + 255) / 256, 256>>>(SPL, ft_b, out + out_off, OUTC);
}

extern "C" void kernel_launch(void* const* d_in, const int* in_sizes, int n_in,
                              void* d_out, int out_size)
{
    const float* tokens     = (const float*)d_in[0];
    const float* cls_tokens = (const float*)d_in[1];
    const float* a_qkv_w    = (const float*)d_in[2];
    const float* a_qkv_b    = (const float*)d_in[3];
    const float* af_qkv_w   = (const float*)d_in[4];
    const float* af_qkv_b   = (const float*)d_in[5];
    const float* b_qkv_w    = (const float*)d_in[6];
    const float* b_qkv_b    = (const float*)d_in[7];
    const float* bf_qkv_w   = (const float*)d_in[8];
    const float* bf_qkv_b   = (const float*)d_in[9];
    const float* atW_w      = (const float*)d_in[10];
    const float* atW_b      = (const float*)d_in[11];
    const float* afW_w      = (const float*)d_in[12];
    const float* afW_b      = (const float*)d_in[13];
    const float* btW_w      = (const float*)d_in[14];
    const float* btW_b      = (const float*)d_in[15];
    const float* bfW_w      = (const float*)d_in[16];
    const float* bfW_b      = (const float*)d_in[17];
    const float* aft_w      = (const float*)d_in[18];
    const float* aft_b      = (const float*)d_in[19];
    const float* bft_w      = (const float*)d_in[20];
    const float* bft_b      = (const float*)d_in[21];
    const float* fnn1_w     = (const float*)d_in[22];
    const float* fnn1_b     = (const float*)d_in[23];
    const float* fnn2_w     = (const float*)d_in[24];
    const float* fnn2_b     = (const float*)d_in[25];

    float* out = (float*)d_out;

    run_branch(tokens, LA, a_qkv_w, a_qkv_b, af_qkv_w, af_qkv_b,
               atW_w, atW_b, afW_w, afW_b, aft_w, aft_b, out, NC);

    run_branch(cls_tokens, MAXL, b_qkv_w, b_qkv_b, bf_qkv_w, bf_qkv_b,
               btW_w, btW_b, bfW_w, bfW_b, bft_w, bft_b, out, NC + 1000);

    // ---- FNN head -> out cols [0, 3) ----
    float* Hc = sym(g_H);
    float* T1 = sym(g_T1);
    build_h<<<(BB * 2 * HH + 255) / 256, 256>>>(tokens, cls_tokens, Hc);
    launch_gemm(Hc, fnn1_w, T1, fnn1_b, BB, HH, 2 * HH, 1,
                0, 2 * HH, 1, 0, HH, 1, 0, HH, 1.0f);
    launch_gemm(T1, fnn2_w, out, fnn2_b, BB, NC, HH, 1,
                0, HH, 1, 0, NC, 1, 0, OUTC, 1.0f);
}

// round 14
// speedup vs baseline: 3.7214x; 1.3952x over previous
#include <cuda_runtime.h>
#include <stdint.h>

// Problem constants
#define BB   64
#define HH   768
#define MAXL 256
#define QL   16
#define LA   272   // MAXL + QL
#define NC   3
#define OUTC 2003  // NC + 1000 + 1000

// GEMM tiling
#define BM 128
#define BN 128
#define BK 16
#define RS 134          // padded smem row stride (floats): conflict-free STS both modes
#define NSPLIT 16

// ---------------- scratch (device globals; no allocation) ----------------
__device__ float g_X   [BB * LA * HH];
__device__ float g_Q   [BB * LA * HH];
__device__ float g_K   [BB * LA * HH];
__device__ float g_V   [BB * LA * HH];
__device__ float g_ATTN[BB * HH * HH];
__device__ float g_TSA [BB * LA * HH];
__device__ float g_FSA [BB * HH * LA];
__device__ float g_T   [BB * LA * 100];
__device__ float g_F   [BB * LA * 100];
__device__ float g_TF  [BB * 100 * 100];
__device__ float g_H   [BB * 2 * HH];
__device__ float g_T1  [BB * HH];
__device__ float g_SPL [NSPLIT * BB * 1000];

__device__ __forceinline__ unsigned f2tf32(float x)
{
    unsigned u;
    asm("cvt.rna.tf32.f32 %0, %1;" : "=r"(u) : "f"(x));
    return u;
}

__device__ __forceinline__ void mma_tf32(float* d, const unsigned* a, unsigned b0, unsigned b1)
{
    asm("mma.sync.aligned.m16n8k8.row.col.f32.tf32.tf32.f32 "
        "{%0,%1,%2,%3}, {%4,%5,%6,%7}, {%8,%9}, {%0,%1,%2,%3};\n"
        : "+f"(d[0]), "+f"(d[1]), "+f"(d[2]), "+f"(d[3])
        : "r"(a[0]), "r"(a[1]), "r"(a[2]), "r"(a[3]), "r"(b0), "r"(b1));
}

// ---------------- generic strided batched TF32 tensor-core GEMM ----------------
// C[b, m, n] = alpha * sum_k A[.] * B[.] + bias[n]
// if splitK > 0: bz is the split index; C += bz*sCb; k in [bz*splitK, min(K, ...))
// R13: same as R12 but with the FIXED fast-path base pointers — Af/Bf must
// include the CTA tile offsets bm*sAm / bn*sBn (offA/offB are tile-relative).
__global__ __launch_bounds__(256) void gemm_tf32(
    const float* __restrict__ A, const float* __restrict__ Bm,
    float* __restrict__ C, const float* __restrict__ bias,
    int M, int N, int K,
    long sAb, long sAm, long sAk,
    long sBb, long sBk, long sBn,
    long sCb, long sCm,
    float alpha, int splitK)
{
    __shared__ float As[2][BK * RS];
    __shared__ float Bs[2][BK * RS];

    const int bz = blockIdx.z;
    int kBeg = 0, kEnd = K;
    if (splitK > 0) {
        kBeg = bz * splitK;
        kEnd = min(K, kBeg + splitK);
        C += (long)bz * sCb;
    } else {
        A  += (long)bz * sAb;
        Bm += (long)bz * sBb;
        C  += (long)bz * sCb;
    }

    const int bm = blockIdx.y * BM;
    const int bn = blockIdx.x * BN;
    const int tid  = threadIdx.x;
    const int lane = tid & 31;
    const int wid  = tid >> 5;
    const int wm   = wid & 3;    // 4 m-warps  -> 32 rows each
    const int wn   = wid >> 2;   // 2 n-warps  -> 64 cols each
    const int g    = lane >> 2;  // 0..7
    const int t4   = lane & 3;   // 0..3

    // Per-operand load indexing mode: k-fast when k-stride is 1 (coalesced),
    // else row-fast (coalesced when row-stride is 1).
    const bool aKf = (sAk == 1);
    const bool bKf = (sBk == 1);

    int amI[8], akI[8], bnI[8], bkI[8];
    int stsA[8], stsB[8];
    long offA[8], offB[8];
    #pragma unroll
    for (int t = 0; t < 8; t++) {
        int e = tid + t * 256;     // 0..2047
        amI[t] = aKf ? (e >> 4)  : (e & 127);
        akI[t] = aKf ? (e & 15)  : (e >> 7);
        bnI[t] = bKf ? (e >> 4)  : (e & 127);
        bkI[t] = bKf ? (e & 15)  : (e >> 7);
        stsA[t] = akI[t] * RS + amI[t];
        stsB[t] = bkI[t] * RS + bnI[t];
        offA[t] = (long)amI[t] * sAm + (long)akI[t] * sAk;
        offB[t] = (long)bnI[t] * sBn + (long)bkI[t] * sBk;
    }

    // fast path: entire tile in bounds and K range a multiple of BK
    const bool fast = (bm + BM <= M) && (bn + BN <= N) &&
                      (((kEnd - kBeg) & (BK - 1)) == 0);

    float acc[2][8][4];
    #pragma unroll
    for (int i = 0; i < 2; i++)
        #pragma unroll
        for (int j = 0; j < 8; j++)
            #pragma unroll
            for (int q = 0; q < 4; q++) acc[i][j][q] = 0.f;

    float pa[8], pb[8];

    // FIX (R12 bug): include the CTA tile base in the fast-path pointers.
    const float* Af = A + (long)bm * sAm + (long)kBeg * sAk;
    const float* Bf = Bm + (long)bn * sBn + (long)kBeg * sBk;

    const int nIter = (kEnd - kBeg + BK - 1) / BK;

    // prologue load (tile 0)
    if (fast) {
        #pragma unroll
        for (int t = 0; t < 8; t++) { pa[t] = Af[offA[t]]; pb[t] = Bf[offB[t]]; }
    } else {
        #pragma unroll
        for (int t = 0; t < 8; t++) {
            int gm = bm + amI[t], gka = kBeg + akI[t];
            pa[t] = (gm < M && gka < kEnd) ? A[(long)gm * sAm + (long)gka * sAk] : 0.f;
            int gn = bn + bnI[t], gkb = kBeg + bkI[t];
            pb[t] = (gn < N && gkb < kEnd) ? Bm[(long)gkb * sBk + (long)gn * sBn] : 0.f;
        }
    }

    int buf = 0;
    for (int it = 0; it < nIter; ++it) {
        // commit current tile to smem (convert to tf32 bits)
        #pragma unroll
        for (int t = 0; t < 8; t++) {
            As[buf][stsA[t]] = __uint_as_float(f2tf32(pa[t]));
            Bs[buf][stsB[t]] = __uint_as_float(f2tf32(pb[t]));
        }
        __syncthreads();

        // prefetch next tile into registers (overlaps with compute below)
        if (it + 1 < nIter) {
            if (fast) {
                Af += (long)BK * sAk;
                Bf += (long)BK * sBk;
                #pragma unroll
                for (int t = 0; t < 8; t++) { pa[t] = Af[offA[t]]; pb[t] = Bf[offB[t]]; }
            } else {
                int k0 = kBeg + (it + 1) * BK;
                #pragma unroll
                for (int t = 0; t < 8; t++) {
                    int gm = bm + amI[t], gka = k0 + akI[t];
                    pa[t] = (gm < M && gka < kEnd) ? A[(long)gm * sAm + (long)gka * sAk] : 0.f;
                    int gn = bn + bnI[t], gkb = k0 + bkI[t];
                    pb[t] = (gn < N && gkb < kEnd) ? Bm[(long)gkb * sBk + (long)gn * sBn] : 0.f;
                }
            }
        }

        // compute: two k8 steps from the current buffer
        #pragma unroll
        for (int ks = 0; ks < BK; ks += 8) {
            unsigned a[2][4];
            #pragma unroll
            for (int tm = 0; tm < 2; tm++) {
                int mr = wm * 32 + tm * 16;
                a[tm][0] = __float_as_uint(As[buf][(ks + t4    ) * RS + mr + g    ]);
                a[tm][1] = __float_as_uint(As[buf][(ks + t4    ) * RS + mr + g + 8]);
                a[tm][2] = __float_as_uint(As[buf][(ks + t4 + 4) * RS + mr + g    ]);
                a[tm][3] = __float_as_uint(As[buf][(ks + t4 + 4) * RS + mr + g + 8]);
            }
            #pragma unroll
            for (int tn = 0; tn < 8; tn++) {
                int nc = wn * 64 + tn * 8 + g;
                unsigned b0 = __float_as_uint(Bs[buf][(ks + t4    ) * RS + nc]);
                unsigned b1 = __float_as_uint(Bs[buf][(ks + t4 + 4) * RS + nc]);
                mma_tf32(acc[0][tn], a[0], b0, b1);
                mma_tf32(acc[1][tn], a[1], b0, b1);
            }
        }
        buf ^= 1;
        // no second sync: iter it+1 writes the other buffer; reads of that
        // buffer (iter it-1) completed before this iter's top-of-loop sync.
    }

    // epilogue
    #pragma unroll
    for (int tm = 0; tm < 2; tm++) {
        int r0 = bm + wm * 32 + tm * 16 + g;
        int r1 = r0 + 8;
        #pragma unroll
        for (int tn = 0; tn < 8; tn++) {
            int cb = bn + wn * 64 + tn * 8 + 2 * t4;
            float v0 = acc[tm][tn][0] * alpha;
            float v1 = acc[tm][tn][1] * alpha;
            float v2 = acc[tm][tn][2] * alpha;
            float v3 = acc[tm][tn][3] * alpha;
            if (bias) {
                float b0 = (cb     < N) ? bias[cb]     : 0.f;
                float b1 = (cb + 1 < N) ? bias[cb + 1] : 0.f;
                v0 += b0; v1 += b1; v2 += b0; v3 += b1;
            }
            if (r0 < M) {
                if (cb     < N) C[(long)r0 * sCm + cb    ] = v0;
                if (cb + 1 < N) C[(long)r0 * sCm + cb + 1] = v1;
            }
            if (r1 < M) {
                if (cb     < N) C[(long)r1 * sCm + cb    ] = v2;
                if (cb + 1 < N) C[(long)r1 * sCm + cb + 1] = v3;
            }
        }
    }
}

// ---------------- split-K reduction (deterministic) ----------------
__global__ void splitk_reduce(const float* __restrict__ part, const float* __restrict__ bias,
                              float* __restrict__ out, long sCm)
{
    int i = blockIdx.x * 256 + threadIdx.x;  // over 64*1000
    if (i >= BB * 1000) return;
    int m = i / 1000, n = i % 1000;
    float s = bias[n];
    #pragma unroll
    for (int sp = 0; sp < NSPLIT; sp++) s += part[(long)sp * (BB * 1000) + i];
    out[(long)m * sCm + n] = s;
}

// ---------------- row softmax (in place) ----------------
__global__ void softmax_rows(float* __restrict__ x, int n)
{
    long r = blockIdx.x;
    float* p = x + r * (long)n;
    __shared__ float sd[256];
    int t = threadIdx.x;

    float m = -3.4e38f;
    for (int i = t; i < n; i += 256) m = fmaxf(m, p[i]);
    sd[t] = m; __syncthreads();
    for (int s = 128; s > 0; s >>= 1) { if (t < s) sd[t] = fmaxf(sd[t], sd[t + s]); __syncthreads(); }
    m = sd[0]; __syncthreads();

    float sum = 0.f;
    for (int i = t; i < n; i += 256) { float e = __expf(p[i] - m); p[i] = e; sum += e; }
    sd[t] = sum; __syncthreads();
    for (int s = 128; s > 0; s >>= 1) { if (t < s) sd[t] += sd[t + s]; __syncthreads(); }
    float inv = 1.0f / sd[0];

    for (int i = t; i < n; i += 256) p[i] *= inv;
}

// ---------------- copy tokens[:,1:,:] -> X ----------------
__global__ void strip_first(const float* __restrict__ src, float* __restrict__ dst,
                            int rows_in, int rows_out)
{
    long i = (long)blockIdx.x * blockDim.x + threadIdx.x;
    long total = (long)BB * rows_out * HH;
    if (i >= total) return;
    int d = (int)(i % HH);
    long tmp = i / HH;
    int l = (int)(tmp % rows_out);
    int b = (int)(tmp / rows_out);
    dst[i] = src[((long)b * rows_in + (l + 1)) * HH + d];
}

// ---------------- build h = concat(tokens[:,0,:], cls_tokens[:,0,:]) ----------------
__global__ void build_h(const float* __restrict__ tok, const float* __restrict__ ctok,
                        float* __restrict__ h)
{
    int i = blockIdx.x * blockDim.x + threadIdx.x;
    if (i >= BB * 2 * HH) return;
    int c = i % (2 * HH);
    int b = i / (2 * HH);
    h[i] = (c < HH) ? tok[(long)b * (LA + 1) * HH + c]
                    : ctok[(long)b * (MAXL + 1) * HH + (c - HH)];
}

// ---------------- host helpers ----------------
static void launch_gemm(const float* A, const float* Bm, float* C, const float* bias,
                        int M, int N, int K, int batch,
                        long sAb, long sAm, long sAk,
                        long sBb, long sBk, long sBn,
                        long sCb, long sCm, float alpha, int splitK = 0)
{
    dim3 grid((N + BN - 1) / BN, (M + BM - 1) / BM, splitK > 0 ? NSPLIT : batch);
    gemm_tf32<<<grid, 256>>>(A, Bm, C, bias, M, N, K,
                             sAb, sAm, sAk, sBb, sBk, sBn, sCb, sCm, alpha, splitK);
}

template <typename T>
static float* sym(T& s)
{
    void* p = nullptr;
    cudaGetSymbolAddress(&p, s);
    return (float*)p;
}

static void run_branch(const float* tokens_full, int S,
                       const float* qkv_w, const float* qkv_b,
                       const float* fqkv_w, const float* fqkv_b,
                       const float* tW_w, const float* tW_b,
                       const float* fW_w, const float* fW_b,
                       const float* ft_w, const float* ft_b,
                       float* out, int out_off)
{
    float* X    = sym(g_X);
    float* Q    = sym(g_Q);
    float* Kb   = sym(g_K);
    float* V    = sym(g_V);
    float* ATTN = sym(g_ATTN);
    float* TSA  = sym(g_TSA);
    float* FSA  = sym(g_FSA);
    float* Tm   = sym(g_T);
    float* Fm   = sym(g_F);
    float* TF   = sym(g_TF);
    float* SPL  = sym(g_SPL);

    const long SH = (long)S * HH;
    const float iscH = rsqrtf((float)HH);
    const float iscS = rsqrtf((float)S);

    {
        long total = (long)BB * S * HH;
        strip_first<<<(int)((total + 255) / 256), 256>>>(tokens_full, X, S + 1, S);
    }

    // ---- time self-attention ----
    float* qkv[3] = {Q, Kb, V};
    for (int j = 0; j < 3; j++) {
        launch_gemm(X, qkv_w + (long)j * HH * HH, qkv[j], qkv_b + (long)j * HH,
                    BB * S, HH, HH, 1,
                    0, HH, 1,
                    0, HH, 1,
                    0, HH, 1.0f);
    }
    launch_gemm(Q, Kb, ATTN, nullptr, S, S, HH, BB,
                SH, HH, 1,
                SH, 1, HH,
                (long)S * S, S, iscH);
    softmax_rows<<<BB * S, 256>>>(ATTN, S);
    launch_gemm(ATTN, V, TSA, nullptr, S, HH, S, BB,
                (long)S * S, S, 1,
                SH, HH, 1,
                SH, HH, 1.0f);

    // ---- feature self-attention ----
    for (int j = 0; j < 3; j++) {
        launch_gemm(X, fqkv_w + (long)j * S * S, qkv[j], fqkv_b + (long)j * S,
                    HH, S, S, BB,
                    SH, 1, HH,
                    0, S, 1,
                    SH, S, 1.0f);
    }
    launch_gemm(Q, Kb, ATTN, nullptr, HH, HH, S, BB,
                SH, S, 1,
                SH, 1, S,
                (long)HH * HH, HH, iscS);
    softmax_rows<<<BB * HH, 256>>>(ATTN, HH);
    launch_gemm(ATTN, V, FSA, nullptr, HH, S, HH, BB,
                (long)HH * HH, HH, 1,
                SH, S, 1,
                SH, S, 1.0f);

    // ---- projections to 100 ----
    launch_gemm(TSA, tW_w, Tm, tW_b, BB * S, 100, HH, 1,
                0, HH, 1, 0, 100, 1, 0, 100, 1.0f);
    launch_gemm(FSA, fW_w, Fm, fW_b, S, 100, HH, BB,
                SH, 1, S,
                0, 100, 1,
                (long)S * 100, 100, 1.0f);

    // ---- TF[b,m,n] = sum_l T[b,l,m] * F[b,l,n] ----
    launch_gemm(Tm, Fm, TF, nullptr, 100, 100, S, BB,
                (long)S * 100, 1, 100,
                (long)S * 100, 100, 1,
                10000, 100, 1.0f);

    // ---- big final GEMM via deterministic split-K ----
    int chunk = ((10000 + NSPLIT * BK - 1) / (NSPLIT * BK)) * BK;  // 640
    launch_gemm(TF, ft_w, SPL, nullptr, BB, 1000, 10000, 1,
                0, 10000, 1,
                0, 1000, 1,
                (long)BB * 1000, 1000, 1.0f, chunk);
    splitk_reduce<<<(BB * 1000 + 255) / 256, 256>>>(SPL, ft_b, out + out_off, OUTC);
}

extern "C" void kernel_launch(void* const* d_in, const int* in_sizes, int n_in,
                              void* d_out, int out_size)
{
    const float* tokens     = (const float*)d_in[0];
    const float* cls_tokens = (const float*)d_in[1];
    const float* a_qkv_w    = (const float*)d_in[2];
    const float* a_qkv_b    = (const float*)d_in[3];
    const float* af_qkv_w   = (const float*)d_in[4];
    const float* af_qkv_b   = (const float*)d_in[5];
    const float* b_qkv_w    = (const float*)d_in[6];
    const float* b_qkv_b    = (const float*)d_in[7];
    const float* bf_qkv_w   = (const float*)d_in[8];
    const float* bf_qkv_b   = (const float*)d_in[9];
    const float* atW_w      = (const float*)d_in[10];
    const float* atW_b      = (const float*)d_in[11];
    const float* afW_w      = (const float*)d_in[12];
    const float* afW_b      = (const float*)d_in[13];
    const float* btW_w      = (const float*)d_in[14];
    const float* btW_b      = (const float*)d_in[15];
    const float* bfW_w      = (const float*)d_in[16];
    const float* bfW_b      = (const float*)d_in[17];
    const float* aft_w      = (const float*)d_in[18];
    const float* aft_b      = (const float*)d_in[19];
    const float* bft_w      = (const float*)d_in[20];
    const float* bft_b      = (const float*)d_in[21];
    const float* fnn1_w     = (const float*)d_in[22];
    const float* fnn1_b     = (const float*)d_in[23];
    const float* fnn2_w     = (const float*)d_in[24];
    const float* fnn2_b     = (const float*)d_in[25];

    float* out = (float*)d_out;

    run_branch(tokens, LA, a_qkv_w, a_qkv_b, af_qkv_w, af_qkv_b,
               atW_w, atW_b, afW_w, afW_b, aft_w, aft_b, out, NC);

    run_branch(cls_tokens, MAXL, b_qkv_w, b_qkv_b, bf_qkv_w, bf_qkv_b,
               btW_w, btW_b, bfW_w, bfW_b, bft_w, bft_b, out, NC + 1000);

    // ---- FNN head -> out cols [0, 3) ----
    float* Hc = sym(g_H);
    float* T1 = sym(g_T1);
    build_h<<<(BB * 2 * HH + 255) / 256, 256>>>(tokens, cls_tokens, Hc);
    launch_gemm(Hc, fnn1_w, T1, fnn1_b, BB, HH, 2 * HH, 1,
                0, 2 * HH, 1, 0, HH, 1, 0, HH, 1.0f);
    launch_gemm(T1, fnn2_w, out, fnn2_b, BB, NC, HH, 1,
                0, HH, 1, 0, NC, 1, 0, OUTC, 1.0f);
}